// round 7
// baseline (speedup 1.0000x reference)
#include <cuda_runtime.h>
#include <math.h>

// Problem constants (fixed shapes)
constexpr int NN = 100000;   // nodes
constexpr int EE = 1000000;  // edges
constexpr int DD = 80;       // hidden dim
constexpr int HH = 8;        // heads
constexpr int DK = 10;       // per-head dim
constexpr int LL = 10;       // layers

// ---------------- device scratch (no allocations allowed) ----------------
__device__ float g_h[NN * DD];
__device__ float g_q[NN * DD];
__device__ float g_k[NN * DD];
__device__ float g_v[NN * DD];
__device__ float g_attn[NN * DD];
__device__ float g_ffn[NN * 2 * DD];
__device__ float g_score[EE * HH];
__device__ float g_r0[NN * 40];
__device__ float g_r1[NN * 20];
__device__ int g_cnt[NN];
__device__ int g_off[NN + 1];
__device__ int g_cur[NN];
__device__ int g_ssrc[EE];
__device__ int g_sdst[EE];

// ---------------- CSR build ----------------
__global__ void zero_cnt_kernel() {
    int t = blockIdx.x * blockDim.x + threadIdx.x;
    if (t < NN) g_cnt[t] = 0;
}

__global__ void hist_kernel(const int* __restrict__ dst) {
    int e = blockIdx.x * blockDim.x + threadIdx.x;
    if (e < EE) atomicAdd(&g_cnt[dst[e]], 1);
}

// single-block scan: 1024 threads, each owns a contiguous chunk
__global__ void scan_kernel() {
    __shared__ int sums[1024];
    const int t = threadIdx.x;
    const int CH = (NN + 1023) / 1024;  // 98
    int b = t * CH;
    int e2 = b + CH; if (e2 > NN) e2 = NN;
    int s = 0;
    for (int i = b; i < e2; i++) s += g_cnt[i];
    sums[t] = s;
    __syncthreads();
    for (int ofs = 1; ofs < 1024; ofs <<= 1) {
        int v = (t >= ofs) ? sums[t - ofs] : 0;
        __syncthreads();
        sums[t] += v;
        __syncthreads();
    }
    int run = (t > 0) ? sums[t - 1] : 0;
    for (int i = b; i < e2; i++) {
        g_off[i] = run;
        g_cur[i] = run;
        run += g_cnt[i];
    }
    if (t == 1023) g_off[NN] = run;
}

__global__ void scatter_kernel(const int* __restrict__ src, const int* __restrict__ dst) {
    int e = blockIdx.x * blockDim.x + threadIdx.x;
    if (e >= EE) return;
    int d = dst[e];
    int p = atomicAdd(&g_cur[d], 1);
    g_ssrc[p] = src[e];
    g_sdst[p] = d;
}

// ---------------- tiled GEMM: C[M,NC] = act(A[M,KTOT] @ W + bias (+res)) ----------------
// Block: 256 threads (16x16), 64 rows x NC cols per block. K chunked at 80 so
// static smem stays under 48KB. Register blocking 4 rows x (NC/16) cols.
template <int KTOT, int NC, bool BIAS, bool RELU, int NRES>
__global__ void __launch_bounds__(256)
gemm_tiled(const float* __restrict__ A, int lda,
           const float* __restrict__ W, int ldw,
           const float* __restrict__ bias,
           const float* __restrict__ res,
           float* __restrict__ C, int ldc, int M) {
    constexpr int KT = (KTOT > 80) ? 80 : KTOT;
    static_assert(KTOT <= 80 || (KTOT % 80) == 0, "K chunking");
    constexpr int TN = NC / 16;
    __shared__ __align__(16) float Ws[KT * NC];
    __shared__ __align__(16) float As[KT * 64];

    const int tid = threadIdx.x;
    const int tx = tid & 15;
    const int ty = tid >> 4;
    const int row0 = blockIdx.x * 64;

    float acc[4][TN];
#pragma unroll
    for (int i = 0; i < 4; i++)
#pragma unroll
        for (int j = 0; j < TN; j++) acc[i][j] = 0.f;

    for (int k0 = 0; k0 < KTOT; k0 += KT) {
        // load weight chunk [KT x NC]
        for (int idx = tid; idx < KT * NC; idx += 256) {
            int kk = idx / NC, c = idx - kk * NC;
            Ws[idx] = W[(k0 + kk) * ldw + c];
        }
        // load A tile, transposed to [KT][64]
        for (int idx = tid; idx < 64 * KT; idx += 256) {
            int r = idx / KT, kk = idx - r * KT;
            int gr = row0 + r;
            As[kk * 64 + r] = (gr < M) ? A[gr * lda + k0 + kk] : 0.f;
        }
        __syncthreads();
#pragma unroll 4
        for (int k = 0; k < KT; ++k) {
            float4 av = *reinterpret_cast<const float4*>(&As[k * 64 + ty * 4]);
#pragma unroll
            for (int j = 0; j < TN; ++j) {
                float w = Ws[k * NC + tx + j * 16];
                acc[0][j] = fmaf(av.x, w, acc[0][j]);
                acc[1][j] = fmaf(av.y, w, acc[1][j]);
                acc[2][j] = fmaf(av.z, w, acc[2][j]);
                acc[3][j] = fmaf(av.w, w, acc[3][j]);
            }
        }
        __syncthreads();
    }

#pragma unroll
    for (int i = 0; i < 4; i++) {
        int gr = row0 + ty * 4 + i;
        if (gr >= M) break;
#pragma unroll
        for (int j = 0; j < TN; j++) {
            int c = tx + j * 16;
            float v = acc[i][j];
            if (BIAS) v += bias[c];
            if (NRES >= 1) v += res[gr * ldc + c];
            if (RELU) v = fmaxf(v, 0.f);
            C[gr * ldc + c] = v;
        }
    }
}

// ---------------- attention: scores over sorted edges ----------------
__global__ void score_kernel() {
    int t = blockIdx.x * blockDim.x + threadIdx.x;
    if (t >= EE * HH) return;
    int j = t >> 3;
    int hd = t & 7;
    int s = g_ssrc[j];
    int d = g_sdst[j];
    const float* kp = g_k + s * DD + hd * DK;
    const float* qp = g_q + d * DD + hd * DK;
    float acc = 0.f;
#pragma unroll
    for (int k = 0; k < DK; k++) acc = fmaf(kp[k], qp[k], acc);
    acc *= 0.31622776601683794f;  // 1/sqrt(10)
    acc = fminf(fmaxf(acc, -5.f), 5.f);
    g_score[t] = expf(acc);
}

// aggregation: thread per (node, dim); segment scan over CSR, fused z-normalize
__global__ void agg_kernel() {
    int lt = threadIdx.x;  // blockDim = 160: two nodes per block
    int half = (lt >= 80) ? 1 : 0;
    int node = blockIdx.x * 2 + half;
    int d = lt - half * 80;
    int h = d / DK;
    int beg = g_off[node];
    int end = g_off[node + 1];
    float wv = 0.f, z = 0.f;
    for (int j = beg; j < end; j++) {
        float s = g_score[j * HH + h];
        wv = fmaf(s, g_v[g_ssrc[j] * DD + d], wv);
        z += s;
    }
    g_attn[node * DD + d] = wv / (z + 1e-6f);
}

// ---------------- small FC (readout stages) ----------------
template <int K, int NC, bool RELU>
__global__ void simple_fc(const float* __restrict__ A, const float* __restrict__ W,
                          const float* __restrict__ b, float* __restrict__ C, int M) {
    int t = blockIdx.x * blockDim.x + threadIdx.x;
    if (t >= M * NC) return;
    int row = t / NC;
    int col = t - row * NC;
    float acc = b[col];
    const float* ap = A + row * K;
#pragma unroll 4
    for (int k = 0; k < K; k++) acc = fmaf(ap[k], W[k * NC + col], acc);
    if (RELU) acc = fmaxf(acc, 0.f);
    C[t] = acc;
}

// ---------------- launcher ----------------
extern "C" void kernel_launch(void* const* d_in, const int* in_sizes, int n_in,
                              void* d_out, int out_size) {
    const float* x   = (const float*)d_in[0];
    const int*   ei  = (const int*)d_in[1];
    const float* We  = (const float*)d_in[2];
    const float* be  = (const float*)d_in[3];
    const float* Wq  = (const float*)d_in[4];
    const float* Wk  = (const float*)d_in[5];
    const float* Wv  = (const float*)d_in[6];
    const float* Wo  = (const float*)d_in[7];
    const float* bo  = (const float*)d_in[8];
    const float* W1  = (const float*)d_in[9];
    const float* b1  = (const float*)d_in[10];
    const float* W2  = (const float*)d_in[11];
    const float* b2  = (const float*)d_in[12];
    const float* Wr0 = (const float*)d_in[13];
    const float* br0 = (const float*)d_in[14];
    const float* Wr1 = (const float*)d_in[15];
    const float* br1 = (const float*)d_in[16];
    const float* Wr2 = (const float*)d_in[17];
    const float* br2 = (const float*)d_in[18];
    float* out = (float*)d_out;

    const int* src = ei;        // edge_index[0]
    const int* dst = ei + EE;   // edge_index[1]

    // resolve device-global scratch addresses
    float *p_h, *p_q, *p_k, *p_v, *p_attn, *p_ffn, *p_r0, *p_r1;
    cudaGetSymbolAddress((void**)&p_h, g_h);
    cudaGetSymbolAddress((void**)&p_q, g_q);
    cudaGetSymbolAddress((void**)&p_k, g_k);
    cudaGetSymbolAddress((void**)&p_v, g_v);
    cudaGetSymbolAddress((void**)&p_attn, g_attn);
    cudaGetSymbolAddress((void**)&p_ffn, g_ffn);
    cudaGetSymbolAddress((void**)&p_r0, g_r0);
    cudaGetSymbolAddress((void**)&p_r1, g_r1);

    const int GB = (NN + 63) / 64;  // 1563 gemm blocks

    // --- CSR build (once per launch) ---
    zero_cnt_kernel<<<(NN + 255) / 256, 256>>>();
    hist_kernel<<<(EE + 255) / 256, 256>>>(dst);
    scan_kernel<<<1, 1024>>>();
    scatter_kernel<<<(EE + 255) / 256, 256>>>(src, dst);

    // --- embedding: h = x @ We + be ---
    gemm_tiled<9, 80, true, false, 0><<<GB, 256>>>(x, 9, We, 80, be, nullptr, p_h, 80, NN);

    // --- layers ---
    for (int l = 0; l < LL; l++) {
        const float* wq = Wq + (size_t)l * DD * DD;
        const float* wk = Wk + (size_t)l * DD * DD;
        const float* wv = Wv + (size_t)l * DD * DD;
        const float* wo = Wo + (size_t)l * DD * DD;
        const float* bol = bo + (size_t)l * DD;
        const float* w1 = W1 + (size_t)l * DD * 2 * DD;
        const float* b1l = b1 + (size_t)l * 2 * DD;
        const float* w2 = W2 + (size_t)l * 2 * DD * DD;
        const float* b2l = b2 + (size_t)l * DD;

        // Q/K/V projections (no bias)
        gemm_tiled<80, 80, false, false, 0><<<GB, 256>>>(p_h, 80, wq, 80, nullptr, nullptr, p_q, 80, NN);
        gemm_tiled<80, 80, false, false, 0><<<GB, 256>>>(p_h, 80, wk, 80, nullptr, nullptr, p_k, 80, NN);
        gemm_tiled<80, 80, false, false, 0><<<GB, 256>>>(p_h, 80, wv, 80, nullptr, nullptr, p_v, 80, NN);

        // edge scores + segment-softmax aggregation
        score_kernel<<<(EE * HH) / 256, 256>>>();
        agg_kernel<<<NN / 2, 160>>>();

        // O-proj + residual (in-place on h)
        gemm_tiled<80, 80, true, false, 1><<<GB, 256>>>(p_attn, 80, wo, 80, bol, p_h, p_h, 80, NN);

        // FFN1: relu(h @ W1 + b1), 160 cols split into two 80-col launches
        gemm_tiled<80, 80, true, true, 0><<<GB, 256>>>(p_h, 80, w1, 160, b1l, nullptr, p_ffn, 160, NN);
        gemm_tiled<80, 80, true, true, 0><<<GB, 256>>>(p_h, 80, w1 + 80, 160, b1l + 80, nullptr, p_ffn + 80, 160, NN);

        // FFN2: h = h + t @ W2 + b2 (K=160 chunked internally)
        gemm_tiled<160, 80, true, false, 1><<<GB, 256>>>(p_ffn, 160, w2, 80, b2l, p_h, p_h, 80, NN);
    }

    // --- readout: 80 -> 40 -> 20 -> 4 ---
    simple_fc<80, 40, true><<<(NN * 40 + 255) / 256, 256>>>(p_h, Wr0, br0, p_r0, NN);
    simple_fc<40, 20, true><<<(NN * 20 + 255) / 256, 256>>>(p_r0, Wr1, br1, p_r1, NN);
    simple_fc<20, 4, false><<<(NN * 4 + 255) / 256, 256>>>(p_r1, Wr2, br2, out, NN);
}

// round 9
// speedup vs baseline: 1.2050x; 1.2050x over previous
#include <cuda_runtime.h>
#include <cuda_bf16.h>
#include <math.h>
#include <stdint.h>

// Problem constants (fixed shapes)
constexpr int NN = 100000;   // nodes
constexpr int EE = 1000000;  // edges
constexpr int DD = 80;       // hidden dim
constexpr int HH = 8;        // heads
constexpr int DK = 10;       // per-head dim
constexpr int LL = 10;       // layers

// ---------------- device scratch (no allocations allowed) ----------------
__device__ float g_h[NN * DD];
__device__ float g_qkv[(size_t)NN * 240];   // q:0..79 k:80..159 v:160..239
__device__ float g_attn[NN * DD];
__device__ float g_ffn[NN * 2 * DD];
__device__ float g_score[EE * HH];
__device__ float g_r0[NN * 40];
__device__ float g_r1[NN * 20];
__device__ int g_cnt[NN];
__device__ int g_off[NN + 1];
__device__ int g_cur[NN];
__device__ int g_ssrc[EE];
__device__ int g_sdst[EE];

// ================= baseline-PTX tensor helpers (sm_80+ features only) ========
__device__ __forceinline__ uint32_t smem_u32(const void* p) {
    uint32_t a;
    asm("{ .reg .u64 t; cvta.to.shared.u64 t, %1; cvt.u32.u64 %0, t; }" : "=r"(a) : "l"(p));
    return a;
}
__device__ __forceinline__ void ldsm_x4(uint32_t* r, uint32_t a) {
    asm volatile("ldmatrix.sync.aligned.m8n8.x4.shared.b16 {%0,%1,%2,%3}, [%4];"
                 : "=r"(r[0]), "=r"(r[1]), "=r"(r[2]), "=r"(r[3]) : "r"(a));
}
__device__ __forceinline__ void ldsm_x2t(uint32_t* r, uint32_t a) {
    asm volatile("ldmatrix.sync.aligned.m8n8.x2.trans.shared.b16 {%0,%1}, [%2];"
                 : "=r"(r[0]), "=r"(r[1]) : "r"(a));
}
__device__ __forceinline__ void mma16816(float* d, const uint32_t* a, const uint32_t* b) {
    asm volatile("mma.sync.aligned.m16n8k16.row.col.f32.bf16.bf16.f32 "
                 "{%0,%1,%2,%3}, {%4,%5,%6,%7}, {%8,%9}, {%0,%1,%2,%3};"
                 : "+f"(d[0]), "+f"(d[1]), "+f"(d[2]), "+f"(d[3])
                 : "r"(a[0]), "r"(a[1]), "r"(a[2]), "r"(a[3]), "r"(b[0]), "r"(b[1]));
}
__device__ __forceinline__ uint32_t split_pack(float x, float y, uint32_t& lo) {
    __nv_bfloat16 hx = __float2bfloat16(x), hy = __float2bfloat16(y);
    __nv_bfloat16 lx = __float2bfloat16(x - __bfloat162float(hx));
    __nv_bfloat16 ly = __float2bfloat16(y - __bfloat162float(hy));
    __nv_bfloat162 lp; lp.x = lx; lp.y = ly;
    lo = *(uint32_t*)&lp;
    __nv_bfloat162 hp; hp.x = hx; hp.y = hy;
    return *(uint32_t*)&hp;
}

// ================= split-bf16 HMMA GEMM =================
// C[M, NB*80] = act(A[M,KTOT] @ [W0|W1|W2] + bias (+res)); 128 rows per CTA.
// smem (dynamic): A_hi | A_lo | B_hi blocks | B_lo blocks. pad-88 rows.
template <int KTOT, int NB, bool BIAS, bool RELU, bool RES>
__global__ void __launch_bounds__(256)
tgemm(const float* __restrict__ A, int lda,
      const float* __restrict__ W0, const float* __restrict__ W1p, const float* __restrict__ W2p,
      int ldw, const float* __restrict__ bias, const float* __restrict__ res,
      float* __restrict__ C, int ldc, int M) {
    extern __shared__ char dsm[];
    constexpr int NCH = KTOT / 80;
    constexpr int NC = NB * 80;
    constexpr int LDS = 88;                        // bf16 elements per padded row
    constexpr uint32_t SA = NCH * 128 * LDS * 2;   // bytes of one A array
    constexpr uint32_t SBB = KTOT * LDS * 2;       // bytes of one B block
    constexpr uint32_t AHI = 0, ALO = SA, BHI = 2 * SA, BLO = 2 * SA + NB * SBB;

    const uint32_t sb = smem_u32(dsm);
    const int tid = threadIdx.x;
    const int warp = tid >> 5;
    const int lane = tid & 31;
    const int row0 = blockIdx.x * 128;

    // ---- stage A (fp32 -> hi/lo bf16), 2 threads per row ----
    {
        const int r = tid >> 1;
        const int half = tid & 1;
        const int gr = row0 + r;
        const float* arow = A + (size_t)gr * lda;
        const int c0 = half * (KTOT / 2);
#pragma unroll
        for (int q = 0; q < KTOT / 8; q++) {
            int k = c0 + q * 4;
            float4 v = (gr < M) ? *(const float4*)(arow + k) : make_float4(0.f, 0.f, 0.f, 0.f);
            int ch = k / 80, kk = k - ch * 80;
            uint32_t off = (ch * 128 * LDS + r * LDS + kk) * 2;
            uint32_t lo0, lo1;
            uint32_t hi0 = split_pack(v.x, v.y, lo0);
            uint32_t hi1 = split_pack(v.z, v.w, lo1);
            *(uint32_t*)(dsm + AHI + off) = hi0;
            *(uint32_t*)(dsm + AHI + off + 4) = hi1;
            *(uint32_t*)(dsm + ALO + off) = lo0;
            *(uint32_t*)(dsm + ALO + off + 4) = lo1;
        }
    }
    // ---- stage B blocks ----
    {
        constexpr int TOT = KTOT * NC;
        for (int idx = tid; idx < TOT; idx += 256) {
            int k = idx / NC;
            int nall = idx - k * NC;
            int nb = nall / 80;
            int n = nall - nb * 80;
            const float* wp = (nb == 0) ? W0 : ((nb == 1) ? W1p : W2p);
            float w = wp[(size_t)k * ldw + n];
            __nv_bfloat16 hi = __float2bfloat16(w);
            __nv_bfloat16 lo = __float2bfloat16(w - __bfloat162float(hi));
            uint32_t off = nb * SBB + ((uint32_t)k * LDS + n) * 2;
            *(__nv_bfloat16*)(dsm + BHI + off) = hi;
            *(__nv_bfloat16*)(dsm + BLO + off) = lo;
        }
    }
    __syncthreads();

    // ---- HMMA mainloop ----
    const int wrow = warp * 16;
    const int j = lane >> 3, ri = lane & 7;
    const int ra = wrow + ri + ((j & 1) << 3);
    const int caoff = (j >> 1) << 3;
    const int rb = lane & 15;
    const int g = lane >> 2, tig = lane & 3;
    const int r0g = row0 + wrow + g;
    const int r1g = r0g + 8;

#pragma unroll 1
    for (int nb = 0; nb < NB; nb++) {
        float acc[10][4];
#pragma unroll
        for (int nt = 0; nt < 10; nt++)
#pragma unroll
            for (int i = 0; i < 4; i++) acc[nt][i] = 0.f;

#pragma unroll
        for (int kc = 0; kc < KTOT / 16; kc++) {
            const int ch = (kc * 16) / 80;
            const int kk = kc * 16 - ch * 80;
            uint32_t aoff = ((uint32_t)ch * 128 * LDS + (uint32_t)ra * LDS + kk + caoff) * 2;
            uint32_t ah[4], al[4];
            ldsm_x4(ah, sb + AHI + aoff);
            ldsm_x4(al, sb + ALO + aoff);
            const uint32_t kg = kc * 16 + rb;
#pragma unroll
            for (int nt = 0; nt < 10; nt++) {
                uint32_t boff = (kg * LDS + nt * 8) * 2;
                uint32_t bh[2], bl[2];
                ldsm_x2t(bh, sb + BHI + nb * SBB + boff);
                ldsm_x2t(bl, sb + BLO + nb * SBB + boff);
                mma16816(acc[nt], ah, bh);
                mma16816(acc[nt], ah, bl);
                mma16816(acc[nt], al, bh);
            }
        }

        // ---- epilogue ----
#pragma unroll
        for (int nt = 0; nt < 10; nt++) {
            int c = nb * 80 + nt * 8 + tig * 2;
            float b0 = BIAS ? bias[c] : 0.f;
            float b1 = BIAS ? bias[c + 1] : 0.f;
            if (r0g < M) {
                float2 o;
                o.x = acc[nt][0] + b0;
                o.y = acc[nt][1] + b1;
                if (RES) {
                    float2 rv = *(const float2*)(res + (size_t)r0g * ldc + c);
                    o.x += rv.x; o.y += rv.y;
                }
                if (RELU) { o.x = fmaxf(o.x, 0.f); o.y = fmaxf(o.y, 0.f); }
                *(float2*)(C + (size_t)r0g * ldc + c) = o;
            }
            if (r1g < M) {
                float2 o;
                o.x = acc[nt][2] + b0;
                o.y = acc[nt][3] + b1;
                if (RES) {
                    float2 rv = *(const float2*)(res + (size_t)r1g * ldc + c);
                    o.x += rv.x; o.y += rv.y;
                }
                if (RELU) { o.x = fmaxf(o.x, 0.f); o.y = fmaxf(o.y, 0.f); }
                *(float2*)(C + (size_t)r1g * ldc + c) = o;
            }
        }
    }
}

// ---------------- CSR build ----------------
__global__ void zero_cnt_kernel() {
    int t = blockIdx.x * blockDim.x + threadIdx.x;
    if (t < NN) g_cnt[t] = 0;
}
__global__ void hist_kernel(const int* __restrict__ dst) {
    int e = blockIdx.x * blockDim.x + threadIdx.x;
    if (e < EE) atomicAdd(&g_cnt[dst[e]], 1);
}
__global__ void scan_kernel() {
    __shared__ int sums[1024];
    const int t = threadIdx.x;
    const int CH = (NN + 1023) / 1024;
    int b = t * CH;
    int e2 = b + CH; if (e2 > NN) e2 = NN;
    int s = 0;
    for (int i = b; i < e2; i++) s += g_cnt[i];
    sums[t] = s;
    __syncthreads();
    for (int ofs = 1; ofs < 1024; ofs <<= 1) {
        int v = (t >= ofs) ? sums[t - ofs] : 0;
        __syncthreads();
        sums[t] += v;
        __syncthreads();
    }
    int run = (t > 0) ? sums[t - 1] : 0;
    for (int i = b; i < e2; i++) {
        g_off[i] = run; g_cur[i] = run; run += g_cnt[i];
    }
    if (t == 1023) g_off[NN] = run;
}
__global__ void scatter_kernel(const int* __restrict__ src, const int* __restrict__ dst) {
    int e = blockIdx.x * blockDim.x + threadIdx.x;
    if (e >= EE) return;
    int d = dst[e];
    int p = atomicAdd(&g_cur[d], 1);
    g_ssrc[p] = src[e];
    g_sdst[p] = d;
}

// ---------------- fp32 tiled GEMM (embedding only, K=9) ----------------
template <int KTOT, int NC, bool BIAS>
__global__ void __launch_bounds__(256)
gemm_tiled(const float* __restrict__ A, int lda,
           const float* __restrict__ W, int ldw,
           const float* __restrict__ bias,
           float* __restrict__ C, int ldc, int M) {
    constexpr int KT = KTOT;
    constexpr int TN = NC / 16;
    __shared__ __align__(16) float Ws[KT * NC];
    __shared__ __align__(16) float As[KT * 64];
    const int tid = threadIdx.x;
    const int tx = tid & 15;
    const int ty = tid >> 4;
    const int row0 = blockIdx.x * 64;
    float acc[4][TN];
#pragma unroll
    for (int i = 0; i < 4; i++)
#pragma unroll
        for (int jj = 0; jj < TN; jj++) acc[i][jj] = 0.f;
    for (int idx = tid; idx < KT * NC; idx += 256) {
        int kk = idx / NC, c = idx - kk * NC;
        Ws[idx] = W[kk * ldw + c];
    }
    for (int idx = tid; idx < 64 * KT; idx += 256) {
        int r = idx / KT, kk = idx - r * KT;
        int gr = row0 + r;
        As[kk * 64 + r] = (gr < M) ? A[gr * lda + kk] : 0.f;
    }
    __syncthreads();
#pragma unroll
    for (int k = 0; k < KT; ++k) {
        float4 av = *reinterpret_cast<const float4*>(&As[k * 64 + ty * 4]);
#pragma unroll
        for (int jj = 0; jj < TN; ++jj) {
            float w = Ws[k * NC + tx + jj * 16];
            acc[0][jj] = fmaf(av.x, w, acc[0][jj]);
            acc[1][jj] = fmaf(av.y, w, acc[1][jj]);
            acc[2][jj] = fmaf(av.z, w, acc[2][jj]);
            acc[3][jj] = fmaf(av.w, w, acc[3][jj]);
        }
    }
#pragma unroll
    for (int i = 0; i < 4; i++) {
        int gr = row0 + ty * 4 + i;
        if (gr >= M) break;
#pragma unroll
        for (int jj = 0; jj < TN; jj++) {
            int c = tx + jj * 16;
            float v = acc[i][jj];
            if (BIAS) v += bias[c];
            C[gr * ldc + c] = v;
        }
    }
}

// ---------------- attention ----------------
__global__ void score_kernel() {
    int t = blockIdx.x * blockDim.x + threadIdx.x;
    if (t >= EE * HH) return;
    int jj = t >> 3;
    int hd = t & 7;
    int s = g_ssrc[jj];
    int d = g_sdst[jj];
    const float* kp = g_qkv + (size_t)s * 240 + 80 + hd * DK;
    const float* qp = g_qkv + (size_t)d * 240 + hd * DK;
    float acc = 0.f;
#pragma unroll
    for (int k = 0; k < DK; k++) acc = fmaf(kp[k], qp[k], acc);
    acc *= 0.31622776601683794f;
    acc = fminf(fmaxf(acc, -5.f), 5.f);
    g_score[t] = expf(acc);
}

__global__ void agg_kernel() {
    int lt = threadIdx.x;  // 160 threads: two nodes/block
    int half = (lt >= 80) ? 1 : 0;
    int node = blockIdx.x * 2 + half;
    int d = lt - half * 80;
    int h = d / DK;
    int beg = g_off[node];
    int end = g_off[node + 1];
    float wv = 0.f, z = 0.f;
    for (int jj = beg; jj < end; jj++) {
        float s = g_score[jj * HH + h];
        wv = fmaf(s, g_qkv[(size_t)g_ssrc[jj] * 240 + 160 + d], wv);
        z += s;
    }
    g_attn[node * DD + d] = wv / (z + 1e-6f);
}

// ---------------- small FC (readout) ----------------
template <int K, int NC, bool RELU>
__global__ void simple_fc(const float* __restrict__ A, const float* __restrict__ W,
                          const float* __restrict__ b, float* __restrict__ C, int M) {
    int t = blockIdx.x * blockDim.x + threadIdx.x;
    if (t >= M * NC) return;
    int row = t / NC;
    int col = t - row * NC;
    float acc = b[col];
    const float* ap = A + row * K;
#pragma unroll 4
    for (int k = 0; k < K; k++) acc = fmaf(ap[k], W[k * NC + col], acc);
    if (RELU) acc = fmaxf(acc, 0.f);
    C[t] = acc;
}

// ---------------- launcher ----------------
extern "C" void kernel_launch(void* const* d_in, const int* in_sizes, int n_in,
                              void* d_out, int out_size) {
    const float* x   = (const float*)d_in[0];
    const int*   ei  = (const int*)d_in[1];
    const float* We  = (const float*)d_in[2];
    const float* be  = (const float*)d_in[3];
    const float* Wq  = (const float*)d_in[4];
    const float* Wk  = (const float*)d_in[5];
    const float* Wv  = (const float*)d_in[6];
    const float* Wo  = (const float*)d_in[7];
    const float* bo  = (const float*)d_in[8];
    const float* W1  = (const float*)d_in[9];
    const float* b1  = (const float*)d_in[10];
    const float* W2  = (const float*)d_in[11];
    const float* b2  = (const float*)d_in[12];
    const float* Wr0 = (const float*)d_in[13];
    const float* br0 = (const float*)d_in[14];
    const float* Wr1 = (const float*)d_in[15];
    const float* br1 = (const float*)d_in[16];
    const float* Wr2 = (const float*)d_in[17];
    const float* br2 = (const float*)d_in[18];
    float* out = (float*)d_out;

    const int* src = ei;
    const int* dst = ei + EE;

    float *p_h, *p_qkv, *p_attn, *p_ffn, *p_r0, *p_r1;
    cudaGetSymbolAddress((void**)&p_h, g_h);
    cudaGetSymbolAddress((void**)&p_qkv, g_qkv);
    cudaGetSymbolAddress((void**)&p_attn, g_attn);
    cudaGetSymbolAddress((void**)&p_ffn, g_ffn);
    cudaGetSymbolAddress((void**)&p_r0, g_r0);
    cudaGetSymbolAddress((void**)&p_r1, g_r1);

    // dynamic smem: 2*A + 2*NB*B  (LDS=88, bf16)
    constexpr int LDSB = 88 * 2;
    constexpr int S_QKV = 2 * (128 * LDSB) + 2 * 3 * (80 * LDSB);   // 129536
    constexpr int S_O   = 2 * (128 * LDSB) + 2 * 1 * (80 * LDSB);   // 73216
    constexpr int S_F1  = 2 * (128 * LDSB) + 2 * 2 * (80 * LDSB);   // 101376
    constexpr int S_F2  = 2 * (2 * 128 * LDSB) + 2 * 1 * (160 * LDSB); // 146432

    cudaFuncSetAttribute((const void*)tgemm<80, 3, false, false, false>,
                         cudaFuncAttributeMaxDynamicSharedMemorySize, S_QKV);
    cudaFuncSetAttribute((const void*)tgemm<80, 1, true, false, true>,
                         cudaFuncAttributeMaxDynamicSharedMemorySize, S_O);
    cudaFuncSetAttribute((const void*)tgemm<80, 2, true, true, false>,
                         cudaFuncAttributeMaxDynamicSharedMemorySize, S_F1);
    cudaFuncSetAttribute((const void*)tgemm<160, 1, true, false, true>,
                         cudaFuncAttributeMaxDynamicSharedMemorySize, S_F2);

    const int TILES = (NN + 127) / 128;  // 782

    // --- CSR build ---
    zero_cnt_kernel<<<(NN + 255) / 256, 256>>>();
    hist_kernel<<<(EE + 255) / 256, 256>>>(dst);
    scan_kernel<<<1, 1024>>>();
    scatter_kernel<<<(EE + 255) / 256, 256>>>(src, dst);

    // --- embedding (fp32, tiny K=9) ---
    gemm_tiled<9, 80, true><<<(NN + 63) / 64, 256>>>(x, 9, We, 80, be, p_h, 80, NN);

    // --- layers ---
    for (int l = 0; l < LL; l++) {
        const float* wq = Wq + (size_t)l * DD * DD;
        const float* wk = Wk + (size_t)l * DD * DD;
        const float* wv = Wv + (size_t)l * DD * DD;
        const float* wo = Wo + (size_t)l * DD * DD;
        const float* bol = bo + (size_t)l * DD;
        const float* w1 = W1 + (size_t)l * DD * 2 * DD;
        const float* b1l = b1 + (size_t)l * 2 * DD;
        const float* w2 = W2 + (size_t)l * 2 * DD * DD;
        const float* b2l = b2 + (size_t)l * DD;

        // fused QKV -> [N, 240]
        tgemm<80, 3, false, false, false><<<TILES, 256, S_QKV>>>(
            p_h, 80, wq, wk, wv, 80, nullptr, nullptr, p_qkv, 240, NN);

        score_kernel<<<(EE * HH) / 256, 256>>>();
        agg_kernel<<<NN / 2, 160>>>();

        // O-proj + bias + residual (in-place on h)
        tgemm<80, 1, true, false, true><<<TILES, 256, S_O>>>(
            p_attn, 80, wo, nullptr, nullptr, 80, bol, p_h, p_h, 80, NN);

        // FFN1: relu(h @ W1 + b1) -> [N, 160]
        tgemm<80, 2, true, true, false><<<TILES, 256, S_F1>>>(
            p_h, 80, w1, w1 + 80, nullptr, 160, b1l, nullptr, p_ffn, 160, NN);

        // FFN2 (K=160) + bias + residual (in-place on h)
        tgemm<160, 1, true, false, true><<<TILES, 256, S_F2>>>(
            p_ffn, 160, w2, nullptr, nullptr, 80, b2l, p_h, p_h, 80, NN);
    }

    // --- readout ---
    simple_fc<80, 40, true><<<(NN * 40 + 255) / 256, 256>>>(p_h, Wr0, br0, p_r0, NN);
    simple_fc<40, 20, true><<<(NN * 20 + 255) / 256, 256>>>(p_r0, Wr1, br1, p_r1, NN);
    simple_fc<20, 4, false><<<(NN * 4 + 255) / 256, 256>>>(p_r1, Wr2, br2, out, NN);
}

// round 10
// speedup vs baseline: 1.5598x; 1.2944x over previous
#include <cuda_runtime.h>
#include <cuda_bf16.h>
#include <math.h>
#include <stdint.h>

// Problem constants (fixed shapes)
constexpr int NN = 100000;   // nodes
constexpr int EE = 1000000;  // edges
constexpr int DD = 80;       // hidden dim
constexpr int HH = 8;        // heads
constexpr int DK = 10;       // per-head dim
constexpr int LL = 10;       // layers

// ---------------- device scratch (no allocations allowed) ----------------
__device__ float g_h[NN * DD];
__device__ float g_qkv[(size_t)NN * 240];   // q:0..79 k:80..159 v:160..239
__device__ float g_attn[NN * DD];
__device__ float g_r0[NN * 40];
__device__ float g_r1[NN * 20];
__device__ int g_cnt[NN];
__device__ int g_off[NN + 1];
__device__ int g_cur[NN];
__device__ int g_ssrc[EE];

// ================= baseline-PTX tensor helpers (sm_80+ features only) ========
__device__ __forceinline__ uint32_t smem_u32(const void* p) {
    uint32_t a;
    asm("{ .reg .u64 t; cvta.to.shared.u64 t, %1; cvt.u32.u64 %0, t; }" : "=r"(a) : "l"(p));
    return a;
}
__device__ __forceinline__ void ldsm_x4(uint32_t* r, uint32_t a) {
    asm volatile("ldmatrix.sync.aligned.m8n8.x4.shared.b16 {%0,%1,%2,%3}, [%4];"
                 : "=r"(r[0]), "=r"(r[1]), "=r"(r[2]), "=r"(r[3]) : "r"(a));
}
__device__ __forceinline__ void ldsm_x4t(uint32_t* r, uint32_t a) {
    asm volatile("ldmatrix.sync.aligned.m8n8.x4.trans.shared.b16 {%0,%1,%2,%3}, [%4];"
                 : "=r"(r[0]), "=r"(r[1]), "=r"(r[2]), "=r"(r[3]) : "r"(a));
}
__device__ __forceinline__ void mma16816(float* d, const uint32_t* a, const uint32_t* b) {
    asm volatile("mma.sync.aligned.m16n8k16.row.col.f32.bf16.bf16.f32 "
                 "{%0,%1,%2,%3}, {%4,%5,%6,%7}, {%8,%9}, {%0,%1,%2,%3};"
                 : "+f"(d[0]), "+f"(d[1]), "+f"(d[2]), "+f"(d[3])
                 : "r"(a[0]), "r"(a[1]), "r"(a[2]), "r"(a[3]), "r"(b[0]), "r"(b[1]));
}
__device__ __forceinline__ uint32_t split_pack(float x, float y, uint32_t& lo) {
    __nv_bfloat16 hx = __float2bfloat16(x), hy = __float2bfloat16(y);
    __nv_bfloat16 lx = __float2bfloat16(x - __bfloat162float(hx));
    __nv_bfloat16 ly = __float2bfloat16(y - __bfloat162float(hy));
    __nv_bfloat162 lp; lp.x = lx; lp.y = ly;
    lo = *(uint32_t*)&lp;
    __nv_bfloat162 hp; hp.x = hx; hp.y = hy;
    return *(uint32_t*)&hp;
}

constexpr int LDS = 88;  // padded bf16 row stride (conflict-free ldmatrix)

// ================= split-bf16 HMMA GEMM (K=80) =================
// C[M, NB*80] = act(A[M,80] @ [W0|W1|W2] + bias (+res)); 128 rows per CTA.
template <int NB, bool BIAS, bool RELU, bool RES>
__global__ void __launch_bounds__(256)
tgemm(const float* __restrict__ A, int lda,
      const float* __restrict__ W0, const float* __restrict__ W1p, const float* __restrict__ W2p,
      int ldw, const float* __restrict__ bias, const float* __restrict__ res,
      float* __restrict__ C, int ldc, int M) {
    extern __shared__ char dsm[];
    constexpr int NC = NB * 80;
    constexpr uint32_t SA = 128 * LDS * 2;   // one A array bytes
    constexpr uint32_t SBB = 80 * LDS * 2;   // one B block bytes
    constexpr uint32_t AHI = 0, ALO = SA, BHI = 2 * SA, BLO = 2 * SA + NB * SBB;

    const uint32_t sb = smem_u32(dsm);
    const int tid = threadIdx.x;
    const int warp = tid >> 5;
    const int lane = tid & 31;
    const int row0 = blockIdx.x * 128;

    // ---- stage A (fp32 -> hi/lo bf16), 2 threads per row ----
    {
        const int r = tid >> 1;
        const int half = tid & 1;
        const int gr = row0 + r;
        const float* arow = A + (size_t)gr * lda;
        const int c0 = half * 40;
#pragma unroll
        for (int q = 0; q < 10; q++) {
            int k = c0 + q * 4;
            float4 v = (gr < M) ? *(const float4*)(arow + k) : make_float4(0.f, 0.f, 0.f, 0.f);
            uint32_t off = ((uint32_t)r * LDS + k) * 2;
            uint32_t lo0, lo1;
            uint32_t hi0 = split_pack(v.x, v.y, lo0);
            uint32_t hi1 = split_pack(v.z, v.w, lo1);
            *(uint32_t*)(dsm + AHI + off) = hi0;
            *(uint32_t*)(dsm + AHI + off + 4) = hi1;
            *(uint32_t*)(dsm + ALO + off) = lo0;
            *(uint32_t*)(dsm + ALO + off + 4) = lo1;
        }
    }
    // ---- stage B blocks ----
    for (int idx = tid; idx < 80 * NC; idx += 256) {
        int k = idx / NC;
        int nall = idx - k * NC;
        int nb = nall / 80;
        int n = nall - nb * 80;
        const float* wp = (nb == 0) ? W0 : ((nb == 1) ? W1p : W2p);
        float w = wp[(size_t)k * ldw + n];
        __nv_bfloat16 hi = __float2bfloat16(w);
        __nv_bfloat16 lo = __float2bfloat16(w - __bfloat162float(hi));
        uint32_t off = nb * SBB + ((uint32_t)k * LDS + n) * 2;
        *(__nv_bfloat16*)(dsm + BHI + off) = hi;
        *(__nv_bfloat16*)(dsm + BLO + off) = lo;
    }
    __syncthreads();

    // ---- HMMA mainloop ----
    const int wrow = warp * 16;
    const int j = lane >> 3, ri = lane & 7;
    const int ra = wrow + ri + ((j & 1) << 3);
    const int caoff = (j >> 1) << 3;
    const int rb = lane & 15;
    const int nq = (lane >> 4) << 3;
    const int g = lane >> 2, tig = lane & 3;
    const int r0g = row0 + wrow + g;
    const int r1g = r0g + 8;

    // hoisted A fragments (5 k-chunks, hi+lo)
    uint32_t ahf[5][4], alf[5][4];
#pragma unroll
    for (int kc = 0; kc < 5; kc++) {
        uint32_t aoff = ((uint32_t)ra * LDS + kc * 16 + caoff) * 2;
        ldsm_x4(ahf[kc], sb + AHI + aoff);
        ldsm_x4(alf[kc], sb + ALO + aoff);
    }

#pragma unroll 1
    for (int nb = 0; nb < NB; nb++) {
        float acc[10][4];
#pragma unroll
        for (int nt = 0; nt < 10; nt++)
#pragma unroll
            for (int i = 0; i < 4; i++) acc[nt][i] = 0.f;

#pragma unroll
        for (int kc = 0; kc < 5; kc++) {
            const uint32_t kg = kc * 16 + rb;
#pragma unroll
            for (int ntp = 0; ntp < 5; ntp++) {
                uint32_t boff = (kg * LDS + ntp * 16 + nq) * 2;
                uint32_t bh[4], bl[4];
                ldsm_x4t(bh, sb + BHI + nb * SBB + boff);
                ldsm_x4t(bl, sb + BLO + nb * SBB + boff);
                mma16816(acc[2 * ntp], ahf[kc], &bh[0]);
                mma16816(acc[2 * ntp], ahf[kc], &bl[0]);
                mma16816(acc[2 * ntp], alf[kc], &bh[0]);
                mma16816(acc[2 * ntp + 1], ahf[kc], &bh[2]);
                mma16816(acc[2 * ntp + 1], ahf[kc], &bl[2]);
                mma16816(acc[2 * ntp + 1], alf[kc], &bh[2]);
            }
        }

        // ---- epilogue ----
#pragma unroll
        for (int nt = 0; nt < 10; nt++) {
            int c = nb * 80 + nt * 8 + tig * 2;
            float b0 = BIAS ? bias[c] : 0.f;
            float b1 = BIAS ? bias[c + 1] : 0.f;
            if (r0g < M) {
                float2 o;
                o.x = acc[nt][0] + b0;
                o.y = acc[nt][1] + b1;
                if (RES) {
                    float2 rv = *(const float2*)(res + (size_t)r0g * ldc + c);
                    o.x += rv.x; o.y += rv.y;
                }
                if (RELU) { o.x = fmaxf(o.x, 0.f); o.y = fmaxf(o.y, 0.f); }
                *(float2*)(C + (size_t)r0g * ldc + c) = o;
            }
            if (r1g < M) {
                float2 o;
                o.x = acc[nt][2] + b0;
                o.y = acc[nt][3] + b1;
                if (RES) {
                    float2 rv = *(const float2*)(res + (size_t)r1g * ldc + c);
                    o.x += rv.x; o.y += rv.y;
                }
                if (RELU) { o.x = fmaxf(o.x, 0.f); o.y = fmaxf(o.y, 0.f); }
                *(float2*)(C + (size_t)r1g * ldc + c) = o;
            }
        }
    }
}

// ================= fused FFN: h += relu(h@W1+b1)@W2+b2 =================
// Intermediate [128x160] stays in registers: accumulator fragments are re-split
// to bf16 hi/lo and consumed directly as A operands of the second MMA chain.
__global__ void __launch_bounds__(256)
ffn_fused(const float* __restrict__ A,
          const float* __restrict__ W1, const float* __restrict__ b1,
          const float* __restrict__ W2, const float* __restrict__ b2,
          float* __restrict__ C, int M) {
    extern __shared__ char dsm[];
    constexpr uint32_t SA = 128 * LDS * 2;       // 22528
    constexpr uint32_t SB1 = 80 * LDS * 2;       // one 80-col block: 14080
    constexpr uint32_t SB2 = 160 * LDS * 2;      // 28160
    constexpr uint32_t AHI = 0, ALO = SA;
    constexpr uint32_t B1HI = 2 * SA;                     // 45056
    constexpr uint32_t B1LO = B1HI + 2 * SB1;             // 73216
    constexpr uint32_t B2HI = B1LO + 2 * SB1;             // 101376
    constexpr uint32_t B2LO = B2HI + SB2;                 // 129536
    // total: 157696

    const uint32_t sb = smem_u32(dsm);
    const int tid = threadIdx.x;
    const int warp = tid >> 5;
    const int lane = tid & 31;
    const int row0 = blockIdx.x * 128;

    // ---- stage A ----
    {
        const int r = tid >> 1;
        const int half = tid & 1;
        const int gr = row0 + r;
        const float* arow = A + (size_t)gr * 80;
        const int c0 = half * 40;
#pragma unroll
        for (int q = 0; q < 10; q++) {
            int k = c0 + q * 4;
            float4 v = (gr < M) ? *(const float4*)(arow + k) : make_float4(0.f, 0.f, 0.f, 0.f);
            uint32_t off = ((uint32_t)r * LDS + k) * 2;
            uint32_t lo0, lo1;
            uint32_t hi0 = split_pack(v.x, v.y, lo0);
            uint32_t hi1 = split_pack(v.z, v.w, lo1);
            *(uint32_t*)(dsm + AHI + off) = hi0;
            *(uint32_t*)(dsm + AHI + off + 4) = hi1;
            *(uint32_t*)(dsm + ALO + off) = lo0;
            *(uint32_t*)(dsm + ALO + off + 4) = lo1;
        }
    }
    // ---- stage W1 [80,160] as two 80-col blocks ----
    for (int idx = tid; idx < 80 * 160; idx += 256) {
        int k = idx / 160;
        int n = idx - k * 160;
        int nb = n / 80, nl = n - nb * 80;
        float w = W1[idx];
        __nv_bfloat16 hi = __float2bfloat16(w);
        __nv_bfloat16 lo = __float2bfloat16(w - __bfloat162float(hi));
        uint32_t off = nb * SB1 + ((uint32_t)k * LDS + nl) * 2;
        *(__nv_bfloat16*)(dsm + B1HI + off) = hi;
        *(__nv_bfloat16*)(dsm + B1LO + off) = lo;
    }
    // ---- stage W2 [160,80] ----
    for (int idx = tid; idx < 160 * 80; idx += 256) {
        int k = idx / 80;
        int n = idx - k * 80;
        float w = W2[idx];
        __nv_bfloat16 hi = __float2bfloat16(w);
        __nv_bfloat16 lo = __float2bfloat16(w - __bfloat162float(hi));
        uint32_t off = ((uint32_t)k * LDS + n) * 2;
        *(__nv_bfloat16*)(dsm + B2HI + off) = hi;
        *(__nv_bfloat16*)(dsm + B2LO + off) = lo;
    }
    __syncthreads();

    const int wrow = warp * 16;
    const int j = lane >> 3, ri = lane & 7;
    const int ra = wrow + ri + ((j & 1) << 3);
    const int caoff = (j >> 1) << 3;
    const int rb = lane & 15;
    const int nq = (lane >> 4) << 3;
    const int g = lane >> 2, tig = lane & 3;
    const int r0g = row0 + wrow + g;
    const int r1g = r0g + 8;

    // A fragments
    uint32_t ahf[5][4], alf[5][4];
#pragma unroll
    for (int kc = 0; kc < 5; kc++) {
        uint32_t aoff = ((uint32_t)ra * LDS + kc * 16 + caoff) * 2;
        ldsm_x4(ahf[kc], sb + AHI + aoff);
        ldsm_x4(alf[kc], sb + ALO + aoff);
    }

    // ---- FFN1: I[128x160] in accumulators (20 n-tiles per warp) ----
    float acc1[20][4];
#pragma unroll
    for (int nt = 0; nt < 20; nt++)
#pragma unroll
        for (int i = 0; i < 4; i++) acc1[nt][i] = 0.f;

#pragma unroll 1
    for (int nb = 0; nb < 2; nb++) {
#pragma unroll
        for (int kc = 0; kc < 5; kc++) {
            const uint32_t kg = kc * 16 + rb;
#pragma unroll
            for (int ntp = 0; ntp < 5; ntp++) {
                uint32_t boff = (kg * LDS + ntp * 16 + nq) * 2;
                uint32_t bh[4], bl[4];
                ldsm_x4t(bh, sb + B1HI + nb * SB1 + boff);
                ldsm_x4t(bl, sb + B1LO + nb * SB1 + boff);
                float* a0 = acc1[nb * 10 + 2 * ntp];
                float* a1 = acc1[nb * 10 + 2 * ntp + 1];
                mma16816(a0, ahf[kc], &bh[0]);
                mma16816(a0, ahf[kc], &bl[0]);
                mma16816(a0, alf[kc], &bh[0]);
                mma16816(a1, ahf[kc], &bh[2]);
                mma16816(a1, ahf[kc], &bl[2]);
                mma16816(a1, alf[kc], &bh[2]);
            }
        }
    }

    // ---- bias + ReLU + split to bf16 A-fragments (in registers) ----
    // acc tile t covers I cols [8t, 8t+8); A-frag k16 tile i uses acc tiles 2i, 2i+1.
    uint32_t ih[10][4], il[10][4];
#pragma unroll
    for (int t = 0; t < 20; t++) {
        int c = t * 8 + tig * 2;
        float b0 = b1[c], bb1 = b1[c + 1];
        float v0 = fmaxf(acc1[t][0] + b0, 0.f);
        float v1 = fmaxf(acc1[t][1] + bb1, 0.f);
        float v2 = fmaxf(acc1[t][2] + b0, 0.f);
        float v3 = fmaxf(acc1[t][3] + bb1, 0.f);
        int i = t >> 1;
        int hiHalf = (t & 1) << 1;   // 0 -> regs 0,1 ; 1 -> regs 2,3
        uint32_t lo0, lo1;
        ih[i][hiHalf + 0] = split_pack(v0, v1, lo0);
        ih[i][hiHalf + 1] = split_pack(v2, v3, lo1);
        il[i][hiHalf + 0] = lo0;
        il[i][hiHalf + 1] = lo1;
    }

    // ---- FFN2: out = I @ W2 (K=160) ----
    float acc2[10][4];
#pragma unroll
    for (int nt = 0; nt < 10; nt++)
#pragma unroll
        for (int i = 0; i < 4; i++) acc2[nt][i] = 0.f;

#pragma unroll
    for (int kc = 0; kc < 10; kc++) {
        const uint32_t kg = kc * 16 + rb;
#pragma unroll
        for (int ntp = 0; ntp < 5; ntp++) {
            uint32_t boff = (kg * LDS + ntp * 16 + nq) * 2;
            uint32_t bh[4], bl[4];
            ldsm_x4t(bh, sb + B2HI + boff);
            ldsm_x4t(bl, sb + B2LO + boff);
            mma16816(acc2[2 * ntp], ih[kc], &bh[0]);
            mma16816(acc2[2 * ntp], ih[kc], &bl[0]);
            mma16816(acc2[2 * ntp], il[kc], &bh[0]);
            mma16816(acc2[2 * ntp + 1], ih[kc], &bh[2]);
            mma16816(acc2[2 * ntp + 1], ih[kc], &bl[2]);
            mma16816(acc2[2 * ntp + 1], il[kc], &bh[2]);
        }
    }

    // ---- epilogue: + b2 + residual(A) ----
#pragma unroll
    for (int nt = 0; nt < 10; nt++) {
        int c = nt * 8 + tig * 2;
        float b0 = b2[c], bb = b2[c + 1];
        if (r0g < M) {
            float2 rv = *(const float2*)(A + (size_t)r0g * 80 + c);
            float2 o;
            o.x = acc2[nt][0] + b0 + rv.x;
            o.y = acc2[nt][1] + bb + rv.y;
            *(float2*)(C + (size_t)r0g * 80 + c) = o;
        }
        if (r1g < M) {
            float2 rv = *(const float2*)(A + (size_t)r1g * 80 + c);
            float2 o;
            o.x = acc2[nt][2] + b0 + rv.x;
            o.y = acc2[nt][3] + bb + rv.y;
            *(float2*)(C + (size_t)r1g * 80 + c) = o;
        }
    }
}

// ---------------- CSR build ----------------
__global__ void zero_cnt_kernel() {
    int t = blockIdx.x * blockDim.x + threadIdx.x;
    if (t < NN) g_cnt[t] = 0;
}
__global__ void hist_kernel(const int* __restrict__ dst) {
    int e = blockIdx.x * blockDim.x + threadIdx.x;
    if (e < EE) atomicAdd(&g_cnt[dst[e]], 1);
}
__global__ void scan_kernel() {
    __shared__ int sums[1024];
    const int t = threadIdx.x;
    const int CH = (NN + 1023) / 1024;
    int b = t * CH;
    int e2 = b + CH; if (e2 > NN) e2 = NN;
    int s = 0;
    for (int i = b; i < e2; i++) s += g_cnt[i];
    sums[t] = s;
    __syncthreads();
    for (int ofs = 1; ofs < 1024; ofs <<= 1) {
        int v = (t >= ofs) ? sums[t - ofs] : 0;
        __syncthreads();
        sums[t] += v;
        __syncthreads();
    }
    int run = (t > 0) ? sums[t - 1] : 0;
    for (int i = b; i < e2; i++) {
        g_off[i] = run; g_cur[i] = run; run += g_cnt[i];
    }
    if (t == 1023) g_off[NN] = run;
}
__global__ void scatter_kernel(const int* __restrict__ src, const int* __restrict__ dst) {
    int e = blockIdx.x * blockDim.x + threadIdx.x;
    if (e >= EE) return;
    int d = dst[e];
    int p = atomicAdd(&g_cur[d], 1);
    g_ssrc[p] = src[e];
}

// ---------------- fused attention: thread = (node, head) ----------------
__global__ void __launch_bounds__(256) attn_fused() {
    __shared__ float sq[32 * 80];
    __shared__ float so[32 * 80];
    const int tid = threadIdx.x;
    const int node0 = blockIdx.x * 32;

    // coalesced Q stage
    for (int idx = tid; idx < 2560; idx += 256) {
        int nl = idx / 80, d = idx - nl * 80;
        sq[idx] = g_qkv[(size_t)(node0 + nl) * 240 + d];
    }
    __syncthreads();

    const int nl = tid >> 3;
    const int h = tid & 7;
    const int node = node0 + nl;
    float q[10];
#pragma unroll
    for (int k = 0; k < 10; k++) q[k] = sq[nl * 80 + h * 10 + k];

    const int beg = g_off[node];
    const int end = g_off[node + 1];
    float z = 0.f, wv[10];
#pragma unroll
    for (int k = 0; k < 10; k++) wv[k] = 0.f;

    for (int jj = beg; jj < end; jj++) {
        int s = g_ssrc[jj];
        const float* kr = g_qkv + (size_t)s * 240 + 80 + h * 10;
        float dot = 0.f;
#pragma unroll
        for (int k = 0; k < 10; k++) dot = fmaf(kr[k], q[k], dot);
        dot = fminf(fmaxf(dot * 0.31622776601683794f, -5.f), 5.f);
        float sc = __expf(dot);
        z += sc;
        const float* vr = kr + 80;
#pragma unroll
        for (int k = 0; k < 10; k++) wv[k] = fmaf(sc, vr[k], wv[k]);
    }
    float inv = 1.f / (z + 1e-6f);
#pragma unroll
    for (int k = 0; k < 10; k++) so[nl * 80 + h * 10 + k] = wv[k] * inv;
    __syncthreads();

    // coalesced output
    for (int idx = tid; idx < 2560; idx += 256)
        g_attn[(size_t)node0 * 80 + idx] = so[idx];
}

// ---------------- fp32 tiled GEMM (embedding only, K=9) ----------------
template <int KTOT, int NC, bool BIAS>
__global__ void __launch_bounds__(256)
gemm_tiled(const float* __restrict__ A, int lda,
           const float* __restrict__ W, int ldw,
           const float* __restrict__ bias,
           float* __restrict__ C, int ldc, int M) {
    constexpr int KT = KTOT;
    constexpr int TN = NC / 16;
    __shared__ __align__(16) float Ws[KT * NC];
    __shared__ __align__(16) float As[KT * 64];
    const int tid = threadIdx.x;
    const int tx = tid & 15;
    const int ty = tid >> 4;
    const int row0 = blockIdx.x * 64;
    float acc[4][TN];
#pragma unroll
    for (int i = 0; i < 4; i++)
#pragma unroll
        for (int jj = 0; jj < TN; jj++) acc[i][jj] = 0.f;
    for (int idx = tid; idx < KT * NC; idx += 256) {
        int kk = idx / NC, c = idx - kk * NC;
        Ws[idx] = W[kk * ldw + c];
    }
    for (int idx = tid; idx < 64 * KT; idx += 256) {
        int r = idx / KT, kk = idx - r * KT;
        int gr = row0 + r;
        As[kk * 64 + r] = (gr < M) ? A[gr * lda + kk] : 0.f;
    }
    __syncthreads();
#pragma unroll
    for (int k = 0; k < KT; ++k) {
        float4 av = *reinterpret_cast<const float4*>(&As[k * 64 + ty * 4]);
#pragma unroll
        for (int jj = 0; jj < TN; ++jj) {
            float w = Ws[k * NC + tx + jj * 16];
            acc[0][jj] = fmaf(av.x, w, acc[0][jj]);
            acc[1][jj] = fmaf(av.y, w, acc[1][jj]);
            acc[2][jj] = fmaf(av.z, w, acc[2][jj]);
            acc[3][jj] = fmaf(av.w, w, acc[3][jj]);
        }
    }
#pragma unroll
    for (int i = 0; i < 4; i++) {
        int gr = row0 + ty * 4 + i;
        if (gr >= M) break;
#pragma unroll
        for (int jj = 0; jj < TN; jj++) {
            int c = tx + jj * 16;
            float v = acc[i][jj];
            if (BIAS) v += bias[c];
            C[gr * ldc + c] = v;
        }
    }
}

// ---------------- small FC (readout) ----------------
template <int K, int NC, bool RELU>
__global__ void simple_fc(const float* __restrict__ A, const float* __restrict__ W,
                          const float* __restrict__ b, float* __restrict__ C, int M) {
    int t = blockIdx.x * blockDim.x + threadIdx.x;
    if (t >= M * NC) return;
    int row = t / NC;
    int col = t - row * NC;
    float acc = b[col];
    const float* ap = A + row * K;
#pragma unroll 4
    for (int k = 0; k < K; k++) acc = fmaf(ap[k], W[k * NC + col], acc);
    if (RELU) acc = fmaxf(acc, 0.f);
    C[t] = acc;
}

// ---------------- launcher ----------------
extern "C" void kernel_launch(void* const* d_in, const int* in_sizes, int n_in,
                              void* d_out, int out_size) {
    const float* x   = (const float*)d_in[0];
    const int*   ei  = (const int*)d_in[1];
    const float* We  = (const float*)d_in[2];
    const float* be  = (const float*)d_in[3];
    const float* Wq  = (const float*)d_in[4];
    const float* Wk  = (const float*)d_in[5];
    const float* Wv  = (const float*)d_in[6];
    const float* Wo  = (const float*)d_in[7];
    const float* bo  = (const float*)d_in[8];
    const float* W1  = (const float*)d_in[9];
    const float* b1  = (const float*)d_in[10];
    const float* W2  = (const float*)d_in[11];
    const float* b2  = (const float*)d_in[12];
    const float* Wr0 = (const float*)d_in[13];
    const float* br0 = (const float*)d_in[14];
    const float* Wr1 = (const float*)d_in[15];
    const float* br1 = (const float*)d_in[16];
    const float* Wr2 = (const float*)d_in[17];
    const float* br2 = (const float*)d_in[18];
    float* out = (float*)d_out;

    const int* src = ei;
    const int* dst = ei + EE;

    float *p_h, *p_qkv, *p_attn, *p_r0, *p_r1;
    cudaGetSymbolAddress((void**)&p_h, g_h);
    cudaGetSymbolAddress((void**)&p_qkv, g_qkv);
    cudaGetSymbolAddress((void**)&p_attn, g_attn);
    cudaGetSymbolAddress((void**)&p_r0, g_r0);
    cudaGetSymbolAddress((void**)&p_r1, g_r1);

    constexpr int SA = 128 * LDS * 2 * 2;        // 45056 (hi+lo)
    constexpr int S_QKV = SA + 3 * 2 * (80 * LDS * 2);   // 129536
    constexpr int S_O   = SA + 1 * 2 * (80 * LDS * 2);   // 73216
    constexpr int S_FFN = 157696;

    cudaFuncSetAttribute((const void*)tgemm<3, false, false, false>,
                         cudaFuncAttributeMaxDynamicSharedMemorySize, S_QKV);
    cudaFuncSetAttribute((const void*)tgemm<1, true, false, true>,
                         cudaFuncAttributeMaxDynamicSharedMemorySize, S_O);
    cudaFuncSetAttribute((const void*)ffn_fused,
                         cudaFuncAttributeMaxDynamicSharedMemorySize, S_FFN);

    const int TILES = (NN + 127) / 128;  // 782

    // --- CSR build ---
    zero_cnt_kernel<<<(NN + 255) / 256, 256>>>();
    hist_kernel<<<(EE + 255) / 256, 256>>>(dst);
    scan_kernel<<<1, 1024>>>();
    scatter_kernel<<<(EE + 255) / 256, 256>>>(src, dst);

    // --- embedding (fp32, tiny K=9) ---
    gemm_tiled<9, 80, true><<<(NN + 63) / 64, 256>>>(x, 9, We, 80, be, p_h, 80, NN);

    // --- layers ---
    for (int l = 0; l < LL; l++) {
        const float* wq = Wq + (size_t)l * DD * DD;
        const float* wk = Wk + (size_t)l * DD * DD;
        const float* wv = Wv + (size_t)l * DD * DD;
        const float* wo = Wo + (size_t)l * DD * DD;
        const float* bol = bo + (size_t)l * DD;
        const float* w1 = W1 + (size_t)l * DD * 2 * DD;
        const float* b1l = b1 + (size_t)l * 2 * DD;
        const float* w2 = W2 + (size_t)l * 2 * DD * DD;
        const float* b2l = b2 + (size_t)l * DD;

        // fused QKV -> [N, 240]
        tgemm<3, false, false, false><<<TILES, 256, S_QKV>>>(
            p_h, 80, wq, wk, wv, 80, nullptr, nullptr, p_qkv, 240, NN);

        // fused score + segment-softmax aggregation
        attn_fused<<<NN / 32, 256>>>();

        // O-proj + bias + residual (in-place on h)
        tgemm<1, true, false, true><<<TILES, 256, S_O>>>(
            p_attn, 80, wo, nullptr, nullptr, 80, bol, p_h, p_h, 80, NN);

        // fused FFN (in-place on h)
        ffn_fused<<<TILES, 256, S_FFN>>>(p_h, w1, b1l, w2, b2l, p_h, NN);
    }

    // --- readout ---
    simple_fc<80, 40, true><<<(NN * 40 + 255) / 256, 256>>>(p_h, Wr0, br0, p_r0, NN);
    simple_fc<40, 20, true><<<(NN * 20 + 255) / 256, 256>>>(p_r0, Wr1, br1, p_r1, NN);
    simple_fc<20, 4, false><<<(NN * 4 + 255) / 256, 256>>>(p_r1, Wr2, br2, out, NN);
}

// round 11
// speedup vs baseline: 1.9647x; 1.2596x over previous
#include <cuda_runtime.h>
#include <cuda_bf16.h>
#include <math.h>
#include <stdint.h>

// Problem constants (fixed shapes)
constexpr int NN = 100000;   // nodes
constexpr int EE = 1000000;  // edges
constexpr int DD = 80;       // hidden dim
constexpr int HH = 8;        // heads
constexpr int DK = 10;       // per-head dim
constexpr int LL = 10;       // layers

// per-layer converted-weight layout (elements): q0 k6400 v12800 o19200 w1 25600 w2 38400, size 51200
constexpr int WPL = 51200;

// ---------------- device scratch (no allocations allowed) ----------------
__device__ __nv_bfloat16 g_hhi[(size_t)NN * 80];
__device__ __nv_bfloat16 g_hlo[(size_t)NN * 80];
__device__ __nv_bfloat16 g_athi[(size_t)NN * 80];
__device__ __nv_bfloat16 g_atlo[(size_t)NN * 80];
__device__ __nv_bfloat16 g_whi[(size_t)LL * WPL];
__device__ __nv_bfloat16 g_wlo[(size_t)LL * WPL];
__device__ float g_qkv[(size_t)NN * 240];   // q:0..79 k:80..159 v:160..239
__device__ float g_r0[NN * 40];
__device__ float g_r1[NN * 20];
__device__ int g_cnt[NN];
__device__ int g_off[NN + 1];
__device__ int g_cur[NN];
__device__ int g_ssrc[EE];

// ================= PTX helpers (sm_80+ baseline features only) ========
__device__ __forceinline__ uint32_t smem_u32(const void* p) {
    uint32_t a;
    asm("{ .reg .u64 t; cvta.to.shared.u64 t, %1; cvt.u32.u64 %0, t; }" : "=r"(a) : "l"(p));
    return a;
}
__device__ __forceinline__ void ldsm_x4(uint32_t* r, uint32_t a) {
    asm volatile("ldmatrix.sync.aligned.m8n8.x4.shared.b16 {%0,%1,%2,%3}, [%4];"
                 : "=r"(r[0]), "=r"(r[1]), "=r"(r[2]), "=r"(r[3]) : "r"(a));
}
__device__ __forceinline__ void ldsm_x4t(uint32_t* r, uint32_t a) {
    asm volatile("ldmatrix.sync.aligned.m8n8.x4.trans.shared.b16 {%0,%1,%2,%3}, [%4];"
                 : "=r"(r[0]), "=r"(r[1]), "=r"(r[2]), "=r"(r[3]) : "r"(a));
}
__device__ __forceinline__ void mma16816(float* d, const uint32_t* a, const uint32_t* b) {
    asm volatile("mma.sync.aligned.m16n8k16.row.col.f32.bf16.bf16.f32 "
                 "{%0,%1,%2,%3}, {%4,%5,%6,%7}, {%8,%9}, {%0,%1,%2,%3};"
                 : "+f"(d[0]), "+f"(d[1]), "+f"(d[2]), "+f"(d[3])
                 : "r"(a[0]), "r"(a[1]), "r"(a[2]), "r"(a[3]), "r"(b[0]), "r"(b[1]));
}
__device__ __forceinline__ void cpa16(uint32_t smem, const void* g) {
    asm volatile("cp.async.cg.shared.global [%0], [%1], 16;" :: "r"(smem), "l"(g));
}
__device__ __forceinline__ void cpa_wait() {
    asm volatile("cp.async.commit_group;");
    asm volatile("cp.async.wait_group 0;" ::: "memory");
}
__device__ __forceinline__ uint32_t split_pack(float x, float y, uint32_t& lo) {
    __nv_bfloat16 hx = __float2bfloat16(x), hy = __float2bfloat16(y);
    __nv_bfloat16 lx = __float2bfloat16(x - __bfloat162float(hx));
    __nv_bfloat16 ly = __float2bfloat16(y - __bfloat162float(hy));
    __nv_bfloat162 lp; lp.x = lx; lp.y = ly;
    lo = *(uint32_t*)&lp;
    __nv_bfloat162 hp; hp.x = hx; hp.y = hy;
    return *(uint32_t*)&hp;
}
__device__ __forceinline__ float2 join2(const __nv_bfloat16* hi, const __nv_bfloat16* lo) {
    __nv_bfloat162 h = *(const __nv_bfloat162*)hi;
    __nv_bfloat162 l = *(const __nv_bfloat162*)lo;
    float2 r;
    r.x = __bfloat162float(h.x) + __bfloat162float(l.x);
    r.y = __bfloat162float(h.y) + __bfloat162float(l.y);
    return r;
}

constexpr int LDS = 88;  // padded bf16 row stride (conflict-free ldmatrix)

// ---------------- weight pre-conversion ----------------
__global__ void conv_w(const float* __restrict__ src, int perL, int dstOff, int total) {
    int t = blockIdx.x * blockDim.x + threadIdx.x;
    if (t >= total) return;
    int l = t / perL, i = t - l * perL;
    float w = src[t];
    __nv_bfloat16 h = __float2bfloat16(w);
    g_whi[(size_t)l * WPL + dstOff + i] = h;
    g_wlo[(size_t)l * WPL + dstOff + i] = __float2bfloat16(w - __bfloat162float(h));
}

// ================= split-bf16 HMMA GEMM (K=80, pre-split inputs) =================
// QKV: NB=3 (phased B staging, 2 slots). O-proj: NB=1 + bias + residual + split out.
template <int NB, bool BIAS, bool RES, bool SPLITOUT>
__global__ void __launch_bounds__(256, 2)
tgemm(const __nv_bfloat16* __restrict__ Ahi, const __nv_bfloat16* __restrict__ Alo,
      const __nv_bfloat16* __restrict__ Whi, const __nv_bfloat16* __restrict__ Wlo,
      const float* __restrict__ bias,
      const __nv_bfloat16* __restrict__ Rhi, const __nv_bfloat16* __restrict__ Rlo,
      float* __restrict__ Cf, int ldc,
      __nv_bfloat16* __restrict__ Chi, __nv_bfloat16* __restrict__ Clo,
      int M) {
    extern __shared__ char dsm[];
    constexpr uint32_t SAB = 128 * LDS * 2;   // 22528 per A array
    constexpr uint32_t SBB = 80 * LDS * 2;    // 14080 per B array
    constexpr uint32_t SLOT = 2 * SBB;        // 28160 (hi+lo)
    constexpr uint32_t BBASE = 2 * SAB;       // 45056

    const uint32_t sb = smem_u32(dsm);
    const int tid = threadIdx.x, warp = tid >> 5, lane = tid & 31;
    const int row0 = blockIdx.x * 128;

    // ---- A stage: pure 16B copies of pre-split rows ----
    {
        const int r = tid >> 1, half = tid & 1;
        const int gr = row0 + r;
        const uint32_t sm0 = sb + (uint32_t)(r * LDS + half * 40) * 2;
        if (gr < M) {
            const char* gh = (const char*)(Ahi + (size_t)gr * 80 + half * 40);
            const char* gl = (const char*)(Alo + (size_t)gr * 80 + half * 40);
#pragma unroll
            for (int q = 0; q < 5; q++) {
                cpa16(sm0 + q * 16, gh + q * 16);
                cpa16(sm0 + SAB + q * 16, gl + q * 16);
            }
        } else {
            uint4 z = {0, 0, 0, 0};
#pragma unroll
            for (int q = 0; q < 5; q++) {
                *(uint4*)(dsm + (r * LDS + half * 40) * 2 + q * 16) = z;
                *(uint4*)(dsm + SAB + (r * LDS + half * 40) * 2 + q * 16) = z;
            }
        }
    }
    // ---- B stage helper: block nb -> slot s ----
    auto stageB = [&](int nb, int s) {
        const uint32_t base = sb + BBASE + s * SLOT;
        for (int idx = tid; idx < 800; idx += 256) {
            int k = idx / 10, q = idx - k * 10;
            uint32_t soff = (uint32_t)(k * LDS + q * 8) * 2;
            cpa16(base + soff, Whi + nb * 6400 + k * 80 + q * 8);
            cpa16(base + SBB + soff, Wlo + nb * 6400 + k * 80 + q * 8);
        }
    };
    stageB(0, 0);
    if (NB >= 2) stageB(1, 1);
    cpa_wait();
    __syncthreads();

    // ---- fragment geometry ----
    const int wrow = warp * 16;
    const int jj = lane >> 3, ri = lane & 7;
    const int ra = wrow + ri + ((jj & 1) << 3);
    const int caoff = (jj >> 1) << 3;
    const int rb = lane & 15;
    const int nq = (lane >> 4) << 3;
    const int g = lane >> 2, tig = lane & 3;
    const int r0g = row0 + wrow + g;
    const int r1g = r0g + 8;

    uint32_t ahf[5][4], alf[5][4];
#pragma unroll
    for (int kc = 0; kc < 5; kc++) {
        uint32_t aoff = ((uint32_t)ra * LDS + kc * 16 + caoff) * 2;
        ldsm_x4(ahf[kc], sb + aoff);
        ldsm_x4(alf[kc], sb + SAB + aoff);
    }

    auto compute = [&](int nb, int s) {
        float acc[10][4];
#pragma unroll
        for (int nt = 0; nt < 10; nt++)
#pragma unroll
            for (int i = 0; i < 4; i++) acc[nt][i] = 0.f;
        const uint32_t bbase = sb + BBASE + s * SLOT;
#pragma unroll
        for (int kc = 0; kc < 5; kc++) {
            const uint32_t kg = kc * 16 + rb;
#pragma unroll
            for (int ntp = 0; ntp < 5; ntp++) {
                uint32_t boff = (kg * LDS + ntp * 16 + nq) * 2;
                uint32_t bh[4], bl[4];
                ldsm_x4t(bh, bbase + boff);
                ldsm_x4t(bl, bbase + SBB + boff);
                mma16816(acc[2 * ntp], ahf[kc], &bh[0]);
                mma16816(acc[2 * ntp], ahf[kc], &bl[0]);
                mma16816(acc[2 * ntp], alf[kc], &bh[0]);
                mma16816(acc[2 * ntp + 1], ahf[kc], &bh[2]);
                mma16816(acc[2 * ntp + 1], ahf[kc], &bl[2]);
                mma16816(acc[2 * ntp + 1], alf[kc], &bh[2]);
            }
        }
        // epilogue
#pragma unroll
        for (int nt = 0; nt < 10; nt++) {
            int cl = nt * 8 + tig * 2;
            int c = nb * 80 + cl;
            float b0 = BIAS ? bias[cl] : 0.f;
            float b1v = BIAS ? bias[cl + 1] : 0.f;
#pragma unroll
            for (int hrow = 0; hrow < 2; hrow++) {
                int gr = hrow ? r1g : r0g;
                if (gr >= M) continue;
                float v0 = acc[nt][hrow * 2 + 0] + b0;
                float v1 = acc[nt][hrow * 2 + 1] + b1v;
                if (RES) {
                    float2 rv = join2(Rhi + (size_t)gr * 80 + cl, Rlo + (size_t)gr * 80 + cl);
                    v0 += rv.x; v1 += rv.y;
                }
                if (SPLITOUT) {
                    uint32_t lo;
                    uint32_t hi = split_pack(v0, v1, lo);
                    *(uint32_t*)(Chi + (size_t)gr * 80 + cl) = hi;
                    *(uint32_t*)(Clo + (size_t)gr * 80 + cl) = lo;
                } else {
                    float2 o; o.x = v0; o.y = v1;
                    *(float2*)(Cf + (size_t)gr * ldc + c) = o;
                }
            }
        }
    };

    compute(0, 0);
    if (NB >= 2) compute(1, 1);
    if (NB == 3) {
        __syncthreads();
        stageB(2, 0);
        cpa_wait();
        __syncthreads();
        compute(2, 0);
    }
}

// ================= fused FFN: h += relu(h@W1+b1)@W2+b2 (pre-split I/O) =========
__global__ void __launch_bounds__(256)
ffn_fused(const __nv_bfloat16* __restrict__ Ahi, const __nv_bfloat16* __restrict__ Alo,
          const __nv_bfloat16* __restrict__ W1hi, const __nv_bfloat16* __restrict__ W1lo,
          const float* __restrict__ b1,
          const __nv_bfloat16* __restrict__ W2hi, const __nv_bfloat16* __restrict__ W2lo,
          const float* __restrict__ b2,
          __nv_bfloat16* __restrict__ Chi, __nv_bfloat16* __restrict__ Clo, int M) {
    extern __shared__ char dsm[];
    constexpr uint32_t SAB = 128 * LDS * 2;   // 22528
    constexpr uint32_t SBB = 80 * LDS * 2;    // 14080
    constexpr uint32_t SLOT = 2 * SBB;        // 28160
    constexpr uint32_t B1 = 2 * SAB;          // 45056 (2 slots)
    constexpr uint32_t B2 = B1 + 2 * SLOT;    // 101376; B2: hi 28160 + lo 28160
    constexpr uint32_t SB2 = 160 * LDS * 2;   // 28160
    // total = 157696

    const uint32_t sb = smem_u32(dsm);
    const int tid = threadIdx.x, warp = tid >> 5, lane = tid & 31;
    const int row0 = blockIdx.x * 128;

    // ---- A stage ----
    {
        const int r = tid >> 1, half = tid & 1;
        const int gr = row0 + r;
        const uint32_t sm0 = sb + (uint32_t)(r * LDS + half * 40) * 2;
        if (gr < M) {
            const char* gh = (const char*)(Ahi + (size_t)gr * 80 + half * 40);
            const char* gl = (const char*)(Alo + (size_t)gr * 80 + half * 40);
#pragma unroll
            for (int q = 0; q < 5; q++) {
                cpa16(sm0 + q * 16, gh + q * 16);
                cpa16(sm0 + SAB + q * 16, gl + q * 16);
            }
        } else {
            uint4 z = {0, 0, 0, 0};
#pragma unroll
            for (int q = 0; q < 5; q++) {
                *(uint4*)(dsm + (r * LDS + half * 40) * 2 + q * 16) = z;
                *(uint4*)(dsm + SAB + (r * LDS + half * 40) * 2 + q * 16) = z;
            }
        }
    }
    // ---- W1 [80,160] as two 80-col slots ----
    for (int idx = tid; idx < 1600; idx += 256) {
        int k = idx / 20, q = idx - k * 20;
        int nb = q / 10, nq8 = q - nb * 10;
        uint32_t soff = (uint32_t)(k * LDS + nq8 * 8) * 2;
        cpa16(sb + B1 + nb * SLOT + soff, W1hi + k * 160 + q * 8);
        cpa16(sb + B1 + nb * SLOT + SBB + soff, W1lo + k * 160 + q * 8);
    }
    // ---- W2 [160,80] ----
    for (int idx = tid; idx < 1600; idx += 256) {
        int k = idx / 10, q = idx - k * 10;
        uint32_t soff = (uint32_t)(k * LDS + q * 8) * 2;
        cpa16(sb + B2 + soff, W2hi + k * 80 + q * 8);
        cpa16(sb + B2 + SB2 + soff, W2lo + k * 80 + q * 8);
    }
    cpa_wait();
    __syncthreads();

    const int wrow = warp * 16;
    const int jj = lane >> 3, ri = lane & 7;
    const int ra = wrow + ri + ((jj & 1) << 3);
    const int caoff = (jj >> 1) << 3;
    const int rb = lane & 15;
    const int nq = (lane >> 4) << 3;
    const int g = lane >> 2, tig = lane & 3;
    const int r0g = row0 + wrow + g;
    const int r1g = r0g + 8;

    uint32_t ahf[5][4], alf[5][4];
#pragma unroll
    for (int kc = 0; kc < 5; kc++) {
        uint32_t aoff = ((uint32_t)ra * LDS + kc * 16 + caoff) * 2;
        ldsm_x4(ahf[kc], sb + aoff);
        ldsm_x4(alf[kc], sb + SAB + aoff);
    }

    // ---- FFN1: I[128x160] in accumulators ----
    float acc1[20][4];
#pragma unroll
    for (int nt = 0; nt < 20; nt++)
#pragma unroll
        for (int i = 0; i < 4; i++) acc1[nt][i] = 0.f;

#pragma unroll 1
    for (int nb = 0; nb < 2; nb++) {
#pragma unroll
        for (int kc = 0; kc < 5; kc++) {
            const uint32_t kg = kc * 16 + rb;
#pragma unroll
            for (int ntp = 0; ntp < 5; ntp++) {
                uint32_t boff = (kg * LDS + ntp * 16 + nq) * 2;
                uint32_t bh[4], bl[4];
                ldsm_x4t(bh, sb + B1 + nb * SLOT + boff);
                ldsm_x4t(bl, sb + B1 + nb * SLOT + SBB + boff);
                float* a0 = acc1[nb * 10 + 2 * ntp];
                float* a1 = acc1[nb * 10 + 2 * ntp + 1];
                mma16816(a0, ahf[kc], &bh[0]);
                mma16816(a0, ahf[kc], &bl[0]);
                mma16816(a0, alf[kc], &bh[0]);
                mma16816(a1, ahf[kc], &bh[2]);
                mma16816(a1, ahf[kc], &bl[2]);
                mma16816(a1, alf[kc], &bh[2]);
            }
        }
    }

    // ---- bias + ReLU + in-register re-split to A fragments ----
    uint32_t ih[10][4], il[10][4];
#pragma unroll
    for (int t = 0; t < 20; t++) {
        int c = t * 8 + tig * 2;
        float b0 = b1[c], bb1 = b1[c + 1];
        float v0 = fmaxf(acc1[t][0] + b0, 0.f);
        float v1 = fmaxf(acc1[t][1] + bb1, 0.f);
        float v2 = fmaxf(acc1[t][2] + b0, 0.f);
        float v3 = fmaxf(acc1[t][3] + bb1, 0.f);
        int i = t >> 1;
        int hf = (t & 1) << 1;
        uint32_t lo0, lo1;
        ih[i][hf + 0] = split_pack(v0, v1, lo0);
        ih[i][hf + 1] = split_pack(v2, v3, lo1);
        il[i][hf + 0] = lo0;
        il[i][hf + 1] = lo1;
    }

    // ---- FFN2 (K=160) ----
    float acc2[10][4];
#pragma unroll
    for (int nt = 0; nt < 10; nt++)
#pragma unroll
        for (int i = 0; i < 4; i++) acc2[nt][i] = 0.f;

#pragma unroll
    for (int kc = 0; kc < 10; kc++) {
        const uint32_t kg = kc * 16 + rb;
#pragma unroll
        for (int ntp = 0; ntp < 5; ntp++) {
            uint32_t boff = (kg * LDS + ntp * 16 + nq) * 2;
            uint32_t bh[4], bl[4];
            ldsm_x4t(bh, sb + B2 + boff);
            ldsm_x4t(bl, sb + B2 + SB2 + boff);
            mma16816(acc2[2 * ntp], ih[kc], &bh[0]);
            mma16816(acc2[2 * ntp], ih[kc], &bl[0]);
            mma16816(acc2[2 * ntp], il[kc], &bh[0]);
            mma16816(acc2[2 * ntp + 1], ih[kc], &bh[2]);
            mma16816(acc2[2 * ntp + 1], ih[kc], &bl[2]);
            mma16816(acc2[2 * ntp + 1], il[kc], &bh[2]);
        }
    }

    // ---- epilogue: + b2 + residual(h) -> split h ----
#pragma unroll
    for (int nt = 0; nt < 10; nt++) {
        int c = nt * 8 + tig * 2;
        float b0 = b2[c], bb = b2[c + 1];
#pragma unroll
        for (int hrow = 0; hrow < 2; hrow++) {
            int gr = hrow ? r1g : r0g;
            if (gr >= M) continue;
            float2 rv = join2(Ahi + (size_t)gr * 80 + c, Alo + (size_t)gr * 80 + c);
            float v0 = acc2[nt][hrow * 2 + 0] + b0 + rv.x;
            float v1 = acc2[nt][hrow * 2 + 1] + bb + rv.y;
            uint32_t lo;
            uint32_t hi = split_pack(v0, v1, lo);
            *(uint32_t*)(Chi + (size_t)gr * 80 + c) = hi;
            *(uint32_t*)(Clo + (size_t)gr * 80 + c) = lo;
        }
    }
}

// ---------------- CSR build ----------------
__global__ void zero_cnt_kernel() {
    int t = blockIdx.x * blockDim.x + threadIdx.x;
    if (t < NN) g_cnt[t] = 0;
}
__global__ void hist_kernel(const int* __restrict__ dst) {
    int e = blockIdx.x * blockDim.x + threadIdx.x;
    if (e < EE) atomicAdd(&g_cnt[dst[e]], 1);
}
__global__ void scan_kernel() {
    __shared__ int sums[1024];
    const int t = threadIdx.x;
    const int CH = (NN + 1023) / 1024;
    int b = t * CH;
    int e2 = b + CH; if (e2 > NN) e2 = NN;
    int s = 0;
    for (int i = b; i < e2; i++) s += g_cnt[i];
    sums[t] = s;
    __syncthreads();
    for (int ofs = 1; ofs < 1024; ofs <<= 1) {
        int v = (t >= ofs) ? sums[t - ofs] : 0;
        __syncthreads();
        sums[t] += v;
        __syncthreads();
    }
    int run = (t > 0) ? sums[t - 1] : 0;
    for (int i = b; i < e2; i++) {
        g_off[i] = run; g_cur[i] = run; run += g_cnt[i];
    }
    if (t == 1023) g_off[NN] = run;
}
__global__ void scatter_kernel(const int* __restrict__ src, const int* __restrict__ dst) {
    int e = blockIdx.x * blockDim.x + threadIdx.x;
    if (e >= EE) return;
    int d = dst[e];
    int p = atomicAdd(&g_cur[d], 1);
    g_ssrc[p] = src[e];
}

// ---------------- fused attention: thread = (node, head), split output -------
__global__ void __launch_bounds__(256) attn_fused() {
    __shared__ float sq[32 * 80];
    __shared__ float so[32 * 80];
    const int tid = threadIdx.x;
    const int node0 = blockIdx.x * 32;

    for (int idx = tid; idx < 2560; idx += 256) {
        int nl = idx / 80, d = idx - nl * 80;
        sq[idx] = g_qkv[(size_t)(node0 + nl) * 240 + d];
    }
    __syncthreads();

    const int nl = tid >> 3;
    const int h = tid & 7;
    const int node = node0 + nl;
    float q[10];
#pragma unroll
    for (int k = 0; k < 10; k++) q[k] = sq[nl * 80 + h * 10 + k];

    const int beg = g_off[node];
    const int end = g_off[node + 1];
    float z = 0.f, wv[10];
#pragma unroll
    for (int k = 0; k < 10; k++) wv[k] = 0.f;

    for (int jj = beg; jj < end; jj++) {
        int s = g_ssrc[jj];
        const float* kr = g_qkv + (size_t)s * 240 + 80 + h * 10;
        float dot = 0.f;
#pragma unroll
        for (int k = 0; k < 10; k++) dot = fmaf(kr[k], q[k], dot);
        dot = fminf(fmaxf(dot * 0.31622776601683794f, -5.f), 5.f);
        float sc = __expf(dot);
        z += sc;
        const float* vr = kr + 80;
#pragma unroll
        for (int k = 0; k < 10; k++) wv[k] = fmaf(sc, vr[k], wv[k]);
    }
    float inv = 1.f / (z + 1e-6f);
#pragma unroll
    for (int k = 0; k < 10; k++) so[nl * 80 + h * 10 + k] = wv[k] * inv;
    __syncthreads();

    for (int idx = tid; idx < 2560; idx += 256) {
        float v = so[idx];
        __nv_bfloat16 hv = __float2bfloat16(v);
        g_athi[(size_t)node0 * 80 + idx] = hv;
        g_atlo[(size_t)node0 * 80 + idx] = __float2bfloat16(v - __bfloat162float(hv));
    }
}

// ---------------- fp32 tiled GEMM (embedding, K=9, split out) ----------------
__global__ void __launch_bounds__(256)
embed_gemm(const float* __restrict__ A, const float* __restrict__ W,
           const float* __restrict__ bias, int M) {
    constexpr int KT = 9, NC = 80;
    __shared__ __align__(16) float Ws[KT * NC];
    __shared__ __align__(16) float As[KT * 64];
    const int tid = threadIdx.x;
    const int tx = tid & 15;
    const int ty = tid >> 4;
    const int row0 = blockIdx.x * 64;
    float acc[4][5];
#pragma unroll
    for (int i = 0; i < 4; i++)
#pragma unroll
        for (int j = 0; j < 5; j++) acc[i][j] = 0.f;
    for (int idx = tid; idx < KT * NC; idx += 256) Ws[idx] = W[idx];
    for (int idx = tid; idx < 64 * KT; idx += 256) {
        int r = idx / KT, kk = idx - r * KT;
        int gr = row0 + r;
        As[kk * 64 + r] = (gr < M) ? A[gr * KT + kk] : 0.f;
    }
    __syncthreads();
#pragma unroll
    for (int k = 0; k < KT; ++k) {
        float4 av = *reinterpret_cast<const float4*>(&As[k * 64 + ty * 4]);
#pragma unroll
        for (int j = 0; j < 5; ++j) {
            float w = Ws[k * NC + tx + j * 16];
            acc[0][j] = fmaf(av.x, w, acc[0][j]);
            acc[1][j] = fmaf(av.y, w, acc[1][j]);
            acc[2][j] = fmaf(av.z, w, acc[2][j]);
            acc[3][j] = fmaf(av.w, w, acc[3][j]);
        }
    }
#pragma unroll
    for (int i = 0; i < 4; i++) {
        int gr = row0 + ty * 4 + i;
        if (gr >= M) break;
#pragma unroll
        for (int j = 0; j < 5; j++) {
            int c = tx + j * 16;
            float v = acc[i][j] + bias[c];
            __nv_bfloat16 hv = __float2bfloat16(v);
            g_hhi[(size_t)gr * 80 + c] = hv;
            g_hlo[(size_t)gr * 80 + c] = __float2bfloat16(v - __bfloat162float(hv));
        }
    }
}

// ---------------- small FC (readout) ----------------
template <int K, int NC, bool RELU>
__global__ void simple_fc(const float* __restrict__ A, const float* __restrict__ W,
                          const float* __restrict__ b, float* __restrict__ C, int M) {
    int t = blockIdx.x * blockDim.x + threadIdx.x;
    if (t >= M * NC) return;
    int row = t / NC;
    int col = t - row * NC;
    float acc = b[col];
    const float* ap = A + (size_t)row * K;
#pragma unroll 4
    for (int k = 0; k < K; k++) acc = fmaf(ap[k], W[k * NC + col], acc);
    if (RELU) acc = fmaxf(acc, 0.f);
    C[t] = acc;
}
// first readout stage reads split h
__global__ void fc_split_in(const float* __restrict__ W, const float* __restrict__ b,
                            float* __restrict__ C, int M) {
    int t = blockIdx.x * blockDim.x + threadIdx.x;
    if (t >= M * 40) return;
    int row = t / 40;
    int col = t - row * 40;
    float acc = b[col];
    const __nv_bfloat16* hh = g_hhi + (size_t)row * 80;
    const __nv_bfloat16* hl = g_hlo + (size_t)row * 80;
#pragma unroll 4
    for (int k = 0; k < 80; k++) {
        float a = __bfloat162float(hh[k]) + __bfloat162float(hl[k]);
        acc = fmaf(a, W[k * 40 + col], acc);
    }
    C[t] = fmaxf(acc, 0.f);
}

// ---------------- launcher ----------------
extern "C" void kernel_launch(void* const* d_in, const int* in_sizes, int n_in,
                              void* d_out, int out_size) {
    const float* x   = (const float*)d_in[0];
    const int*   ei  = (const int*)d_in[1];
    const float* We  = (const float*)d_in[2];
    const float* be  = (const float*)d_in[3];
    const float* Wq  = (const float*)d_in[4];
    const float* Wk  = (const float*)d_in[5];
    const float* Wv  = (const float*)d_in[6];
    const float* Wo  = (const float*)d_in[7];
    const float* bo  = (const float*)d_in[8];
    const float* W1  = (const float*)d_in[9];
    const float* b1  = (const float*)d_in[10];
    const float* W2  = (const float*)d_in[11];
    const float* b2  = (const float*)d_in[12];
    const float* Wr0 = (const float*)d_in[13];
    const float* br0 = (const float*)d_in[14];
    const float* Wr1 = (const float*)d_in[15];
    const float* br1 = (const float*)d_in[16];
    const float* Wr2 = (const float*)d_in[17];
    const float* br2 = (const float*)d_in[18];
    float* out = (float*)d_out;

    const int* src = ei;
    const int* dst = ei + EE;

    __nv_bfloat16 *p_hhi, *p_hlo, *p_athi, *p_atlo, *p_whi, *p_wlo;
    float *p_qkv, *p_r0, *p_r1;
    cudaGetSymbolAddress((void**)&p_hhi, g_hhi);
    cudaGetSymbolAddress((void**)&p_hlo, g_hlo);
    cudaGetSymbolAddress((void**)&p_athi, g_athi);
    cudaGetSymbolAddress((void**)&p_atlo, g_atlo);
    cudaGetSymbolAddress((void**)&p_whi, g_whi);
    cudaGetSymbolAddress((void**)&p_wlo, g_wlo);
    cudaGetSymbolAddress((void**)&p_qkv, g_qkv);
    cudaGetSymbolAddress((void**)&p_r0, g_r0);
    cudaGetSymbolAddress((void**)&p_r1, g_r1);

    constexpr int S_QKV = 45056 + 2 * 28160;   // 101376
    constexpr int S_O   = 45056 + 28160;       // 73216
    constexpr int S_FFN = 157696;
    cudaFuncSetAttribute((const void*)tgemm<3, false, false, false>,
                         cudaFuncAttributeMaxDynamicSharedMemorySize, S_QKV);
    cudaFuncSetAttribute((const void*)tgemm<1, true, true, true>,
                         cudaFuncAttributeMaxDynamicSharedMemorySize, S_O);
    cudaFuncSetAttribute((const void*)ffn_fused,
                         cudaFuncAttributeMaxDynamicSharedMemorySize, S_FFN);

    const int TILES = (NN + 127) / 128;  // 782

    // --- weight pre-conversion (once per launch) ---
    conv_w<<<(LL * 6400 + 255) / 256, 256>>>(Wq, 6400, 0, LL * 6400);
    conv_w<<<(LL * 6400 + 255) / 256, 256>>>(Wk, 6400, 6400, LL * 6400);
    conv_w<<<(LL * 6400 + 255) / 256, 256>>>(Wv, 6400, 12800, LL * 6400);
    conv_w<<<(LL * 6400 + 255) / 256, 256>>>(Wo, 6400, 19200, LL * 6400);
    conv_w<<<(LL * 12800 + 255) / 256, 256>>>(W1, 12800, 25600, LL * 12800);
    conv_w<<<(LL * 12800 + 255) / 256, 256>>>(W2, 12800, 38400, LL * 12800);

    // --- CSR build ---
    zero_cnt_kernel<<<(NN + 255) / 256, 256>>>();
    hist_kernel<<<(EE + 255) / 256, 256>>>(dst);
    scan_kernel<<<1, 1024>>>();
    scatter_kernel<<<(EE + 255) / 256, 256>>>(src, dst);

    // --- embedding (writes split h) ---
    embed_gemm<<<(NN + 63) / 64, 256>>>(x, We, be, NN);

    // --- layers ---
    for (int l = 0; l < LL; l++) {
        const __nv_bfloat16* whi = p_whi + (size_t)l * WPL;
        const __nv_bfloat16* wlo = p_wlo + (size_t)l * WPL;
        const float* bol = bo + (size_t)l * DD;
        const float* b1l = b1 + (size_t)l * 2 * DD;
        const float* b2l = b2 + (size_t)l * DD;

        // fused QKV -> fp32 [N,240]
        tgemm<3, false, false, false><<<TILES, 256, S_QKV>>>(
            p_hhi, p_hlo, whi, wlo, nullptr, nullptr, nullptr,
            p_qkv, 240, nullptr, nullptr, NN);

        attn_fused<<<NN / 32, 256>>>();

        // O-proj + bias + residual -> split h (in place)
        tgemm<1, true, true, true><<<TILES, 256, S_O>>>(
            p_athi, p_atlo, whi + 19200, wlo + 19200, bol, p_hhi, p_hlo,
            nullptr, 0, p_hhi, p_hlo, NN);

        // fused FFN (in place on split h)
        ffn_fused<<<TILES, 256, S_FFN>>>(
            p_hhi, p_hlo, whi + 25600, wlo + 25600, b1l,
            whi + 38400, wlo + 38400, b2l, p_hhi, p_hlo, NN);
    }

    // --- readout 80 -> 40 -> 20 -> 4 ---
    fc_split_in<<<(NN * 40 + 255) / 256, 256>>>(Wr0, br0, p_r0, NN);
    simple_fc<40, 20, true><<<(NN * 20 + 255) / 256, 256>>>(p_r0, Wr1, br1, p_r1, NN);
    simple_fc<20, 4, false><<<(NN * 4 + 255) / 256, 256>>>(p_r1, Wr2, br2, out, NN);
}